// round 1
// baseline (speedup 1.0000x reference)
#include <cuda_runtime.h>

#define SSTEPS 16
#define NN 32768
#define EE 131072

// -------- persistent state (device globals; no allocation allowed) --------
__device__ float g_hs[(size_t)EE * 64];
__device__ float g_cs[(size_t)EE * 64];
__device__ float g_ht[(size_t)NN * 64];
__device__ float g_ct[(size_t)NN * 64];
__device__ float g_hn[(size_t)NN * 128];
__device__ float g_cn[(size_t)NN * 128];
__device__ float g_agg[(size_t)NN * 64];

__device__ __forceinline__ float sigf(float x)   { return 1.f / (1.f + __expf(-x)); }
__device__ __forceinline__ float tanh_f(float x) { return 2.f / (1.f + __expf(-2.f * x)) - 1.f; }
__device__ __forceinline__ float f4c(const float4& v, int kk) {
    return kk == 0 ? v.x : kk == 1 ? v.y : kk == 2 ? v.z : v.w;
}

// ============================================================================
// Edge LSTM (hidden 64): rows M, enc: relu(x[2] @ encw + encb) -> 64
// g = [enc, h] @ [Wih; Whh] + b   (K=128, 256 cols), LSTM update, optional
// scatter of new h into agg via inc (2 incidences per row).
// Block: 64 rows, 256 threads. Warp ty owns rows ty*8..+8; lane tx owns
// column pair tx*2 within each of the 4 gate segments (64 cols each).
// ============================================================================
__global__ __launch_bounds__(256) void edge_lstm_kernel(
    const float* __restrict__ x,
    const float* __restrict__ encw, const float* __restrict__ encb,
    const float* __restrict__ Wih,  const float* __restrict__ Whh,
    const float* __restrict__ bias,
    float* __restrict__ h, float* __restrict__ c,
    float* __restrict__ agg, const int* __restrict__ inc)
{
    __shared__ float As[64][128];   // [row][k]  k: 0..63 enc, 64..127 h
    __shared__ float Bs[16][256];   // k-chunk of combined weights

    const int tid = threadIdx.x;
    const int ty = tid >> 5, tx = tid & 31;
    const int row0 = blockIdx.x * 64;

    // ---- stage A: enc + h (coalesced global, stride-1 STS) ----
    #pragma unroll
    for (int it = 0; it < 16; ++it) {
        int idx = tid + it * 256;
        int j = idx & 63, r = idx >> 6;
        int R = row0 + r;
        float x0 = x[R * 2 + 0], x1 = x[R * 2 + 1];
        As[r][j]      = fmaxf(fmaf(x0, encw[j], fmaf(x1, encw[64 + j], encb[j])), 0.f);
        As[r][64 + j] = h[R * 64 + j];
    }

    // accumulators, initialized with bias
    float aI[8][2], aF[8][2], aG[8][2], aO[8][2];
    {
        float bi0 = bias[tx*2],       bi1 = bias[tx*2+1];
        float bf0 = bias[64 + tx*2],  bf1 = bias[64 + tx*2+1];
        float bg0 = bias[128 + tx*2], bg1 = bias[128 + tx*2+1];
        float bo0 = bias[192 + tx*2], bo1 = bias[192 + tx*2+1];
        #pragma unroll
        for (int r = 0; r < 8; ++r) {
            aI[r][0]=bi0; aI[r][1]=bi1; aF[r][0]=bf0; aF[r][1]=bf1;
            aG[r][0]=bg0; aG[r][1]=bg1; aO[r][0]=bo0; aO[r][1]=bo1;
        }
    }
    __syncthreads();

    for (int kb = 0; kb < 128; kb += 16) {
        // stage B chunk [16][256]
        #pragma unroll
        for (int it = 0; it < 4; ++it) {
            int f = tid + it * 256;
            int k = f >> 6;
            int col = (f & 63) << 2;
            int kg = kb + k;
            const float* src = (kg < 64) ? (Wih + (size_t)kg * 256 + col)
                                         : (Whh + (size_t)(kg - 64) * 256 + col);
            *(float4*)(&Bs[k][col]) = *(const float4*)src;
        }
        __syncthreads();

        #pragma unroll
        for (int k4 = 0; k4 < 4; ++k4) {
            float4 av[8];
            #pragma unroll
            for (int r = 0; r < 8; ++r)
                av[r] = *(const float4*)&As[ty * 8 + r][kb + k4 * 4];
            #pragma unroll
            for (int kk = 0; kk < 4; ++kk) {
                const int k = k4 * 4 + kk;
                float2 bI = *(const float2*)&Bs[k][tx * 2];
                float2 bF = *(const float2*)&Bs[k][64  + tx * 2];
                float2 bG = *(const float2*)&Bs[k][128 + tx * 2];
                float2 bO = *(const float2*)&Bs[k][192 + tx * 2];
                #pragma unroll
                for (int r = 0; r < 8; ++r) {
                    float a = f4c(av[r], kk);
                    aI[r][0] = fmaf(a, bI.x, aI[r][0]); aI[r][1] = fmaf(a, bI.y, aI[r][1]);
                    aF[r][0] = fmaf(a, bF.x, aF[r][0]); aF[r][1] = fmaf(a, bF.y, aF[r][1]);
                    aG[r][0] = fmaf(a, bG.x, aG[r][0]); aG[r][1] = fmaf(a, bG.y, aG[r][1]);
                    aO[r][0] = fmaf(a, bO.x, aO[r][0]); aO[r][1] = fmaf(a, bO.y, aO[r][1]);
                }
            }
        }
        __syncthreads();
    }

    // ---- LSTM epilogue (+ optional scatter into agg) ----
    #pragma unroll
    for (int r = 0; r < 8; ++r) {
        int R = row0 + ty * 8 + r;
        int j = tx * 2;
        float2 cold = *(const float2*)&c[(size_t)R * 64 + j];
        float c0 = sigf(aF[r][0]) * cold.x + sigf(aI[r][0]) * tanh_f(aG[r][0]);
        float c1 = sigf(aF[r][1]) * cold.y + sigf(aI[r][1]) * tanh_f(aG[r][1]);
        float h0 = sigf(aO[r][0]) * tanh_f(c0);
        float h1 = sigf(aO[r][1]) * tanh_f(c1);
        *(float2*)&c[(size_t)R * 64 + j] = make_float2(c0, c1);
        *(float2*)&h[(size_t)R * 64 + j] = make_float2(h0, h1);
        if (agg) {
            int n0 = inc[2 * R], n1 = inc[2 * R + 1];
            atomicAdd(&agg[(size_t)n0 * 64 + j],     h0);
            atomicAdd(&agg[(size_t)n0 * 64 + j + 1], h1);
            atomicAdd(&agg[(size_t)n1 * 64 + j],     h0);
            atomicAdd(&agg[(size_t)n1 * 64 + j + 1], h1);
        }
    }
}

// ============================================================================
// Node kernel: enc = relu(xn * nencw + nencb) (64)
//              emb = relu([ht, agg] @ eew + eeb) (64)
//              g = [enc, emb, hn] @ [Wih; Whh] + b  (K=256, 512 cols, 2 passes)
//              LSTM update (hidden 128) + out = hn @ outw + outb
// ============================================================================
#define AS_STRIDE 260
#define NODE_SMEM_FLOATS (64 * AS_STRIDE + 32 * 256)
#define NODE_SMEM_BYTES  (NODE_SMEM_FLOATS * 4)

__global__ __launch_bounds__(256) void node_kernel(
    const float* __restrict__ xn,
    const float* __restrict__ nencw, const float* __restrict__ nencb,
    const float* __restrict__ eew,   const float* __restrict__ eeb,
    const float* __restrict__ Wih,   const float* __restrict__ Whh,
    const float* __restrict__ bias,
    const float* __restrict__ outw,  const float* __restrict__ outb,
    const float* __restrict__ ht,    const float* __restrict__ agg,
    float* __restrict__ hn, float* __restrict__ cn,
    float* __restrict__ out)
{
    extern __shared__ float sm[];
    float* Asm = sm;                          // [64][AS_STRIDE]: k 0..63 enc, 64..127 emb, 128..255 (ht|agg then hn)
    float* Bsm = sm + 64 * AS_STRIDE;         // [32][256] weight chunk / eew stage (8192 floats)

    const int tid = threadIdx.x;
    const int ty = tid >> 5, tx = tid & 31;
    const int row0 = blockIdx.x * 64;

    // ---- stage enc, ht, agg ----
    #pragma unroll
    for (int it = 0; it < 16; ++it) {
        int idx = tid + it * 256;
        int j = idx & 63, r = idx >> 6;
        int R = row0 + r;
        float xv = xn[R];
        Asm[r * AS_STRIDE + j]       = fmaxf(fmaf(xv, nencw[j], nencb[j]), 0.f);
        Asm[r * AS_STRIDE + 128 + j] = ht[(size_t)R * 64 + j];
        Asm[r * AS_STRIDE + 192 + j] = agg[(size_t)R * 64 + j];
    }
    // stage eew (128x64) into Bsm flat
    #pragma unroll
    for (int it = 0; it < 8; ++it) {
        int f = tid + it * 256;
        *(float4*)&Bsm[f * 4] = *(const float4*)&eew[f * 4];
    }
    __syncthreads();

    // ---- emb GEMM: [64,128] @ [128,64], thread: one row, 16 cols ----
    {
        int r = tid >> 2, jq = tid & 3;     // r in [0,64), jq in [0,4) -> cols jq*16..+16
        float acc[16];
        #pragma unroll
        for (int g = 0; g < 4; ++g)
            #pragma unroll
            for (int u = 0; u < 4; ++u)
                acc[g * 4 + u] = eeb[jq * 16 + g * 4 + u];
        #pragma unroll 4
        for (int k = 0; k < 128; ++k) {
            float a = Asm[r * AS_STRIDE + 128 + k];
            #pragma unroll
            for (int g = 0; g < 4; ++g) {
                float4 w4 = *(const float4*)&Bsm[k * 64 + jq * 16 + g * 4];
                acc[g*4+0] = fmaf(a, w4.x, acc[g*4+0]);
                acc[g*4+1] = fmaf(a, w4.y, acc[g*4+1]);
                acc[g*4+2] = fmaf(a, w4.z, acc[g*4+2]);
                acc[g*4+3] = fmaf(a, w4.w, acc[g*4+3]);
            }
        }
        // write emb to As[.][64..127] (disjoint from the region still being read)
        #pragma unroll
        for (int g = 0; g < 4; ++g)
            #pragma unroll
            for (int u = 0; u < 4; ++u)
                Asm[r * AS_STRIDE + 64 + jq * 16 + g * 4 + u] = fmaxf(acc[g * 4 + u], 0.f);
    }
    __syncthreads();

    // ---- restage hn into As[.][128..255] ----
    #pragma unroll
    for (int it = 0; it < 32; ++it) {
        int idx = tid + it * 256;
        int j = idx & 127, r = idx >> 7;
        Asm[r * AS_STRIDE + 128 + j] = hn[(size_t)(row0 + r) * 128 + j];
    }

    // ---- main GEMM: K=256, 512 cols in 2 passes of 64 cols per gate ----
    float po[8];
    #pragma unroll
    for (int r = 0; r < 8; ++r) po[r] = 0.f;

    for (int p = 0; p < 2; ++p) {
        float aI[8][2], aF[8][2], aG[8][2], aO[8][2];
        {
            int jb = p * 64 + tx * 2;
            float bi0 = bias[jb],       bi1 = bias[jb + 1];
            float bf0 = bias[128 + jb], bf1 = bias[128 + jb + 1];
            float bg0 = bias[256 + jb], bg1 = bias[256 + jb + 1];
            float bo0 = bias[384 + jb], bo1 = bias[384 + jb + 1];
            #pragma unroll
            for (int r = 0; r < 8; ++r) {
                aI[r][0]=bi0; aI[r][1]=bi1; aF[r][0]=bf0; aF[r][1]=bf1;
                aG[r][0]=bg0; aG[r][1]=bg1; aO[r][0]=bo0; aO[r][1]=bo1;
            }
        }
        for (int kb = 0; kb < 256; kb += 32) {
            __syncthreads();
            #pragma unroll
            for (int it = 0; it < 8; ++it) {
                int f = tid + it * 256;
                int k = f >> 6;
                int lc4 = f & 63;
                int G = lc4 >> 4;
                int jj = (lc4 & 15) << 2;
                int gcol = G * 128 + p * 64 + jj;
                int kg = kb + k;
                const float* src = (kg < 128) ? (Wih + (size_t)kg * 512 + gcol)
                                              : (Whh + (size_t)(kg - 128) * 512 + gcol);
                *(float4*)&Bsm[k * 256 + (lc4 << 2)] = *(const float4*)src;
            }
            __syncthreads();
            #pragma unroll
            for (int k4 = 0; k4 < 8; ++k4) {
                float4 av[8];
                #pragma unroll
                for (int r = 0; r < 8; ++r)
                    av[r] = *(const float4*)&Asm[(ty * 8 + r) * AS_STRIDE + kb + k4 * 4];
                #pragma unroll
                for (int kk = 0; kk < 4; ++kk) {
                    const int k = k4 * 4 + kk;
                    float2 bI = *(const float2*)&Bsm[k * 256 + tx * 2];
                    float2 bF = *(const float2*)&Bsm[k * 256 + 64  + tx * 2];
                    float2 bG = *(const float2*)&Bsm[k * 256 + 128 + tx * 2];
                    float2 bO = *(const float2*)&Bsm[k * 256 + 192 + tx * 2];
                    #pragma unroll
                    for (int r = 0; r < 8; ++r) {
                        float a = f4c(av[r], kk);
                        aI[r][0] = fmaf(a, bI.x, aI[r][0]); aI[r][1] = fmaf(a, bI.y, aI[r][1]);
                        aF[r][0] = fmaf(a, bF.x, aF[r][0]); aF[r][1] = fmaf(a, bF.y, aF[r][1]);
                        aG[r][0] = fmaf(a, bG.x, aG[r][0]); aG[r][1] = fmaf(a, bG.y, aG[r][1]);
                        aO[r][0] = fmaf(a, bO.x, aO[r][0]); aO[r][1] = fmaf(a, bO.y, aO[r][1]);
                    }
                }
            }
        }

        // epilogue for this pass's 64 hidden cells
        #pragma unroll
        for (int r = 0; r < 8; ++r) {
            int R = row0 + ty * 8 + r;
            int j = p * 64 + tx * 2;
            float2 cold = *(const float2*)&cn[(size_t)R * 128 + j];
            float c0 = sigf(aF[r][0]) * cold.x + sigf(aI[r][0]) * tanh_f(aG[r][0]);
            float c1 = sigf(aF[r][1]) * cold.y + sigf(aI[r][1]) * tanh_f(aG[r][1]);
            float h0 = sigf(aO[r][0]) * tanh_f(c0);
            float h1 = sigf(aO[r][1]) * tanh_f(c1);
            *(float2*)&cn[(size_t)R * 128 + j] = make_float2(c0, c1);
            *(float2*)&hn[(size_t)R * 128 + j] = make_float2(h0, h1);
            po[r] = fmaf(h0, outw[j],     po[r]);
            po[r] = fmaf(h1, outw[j + 1], po[r]);
        }
    }

    // out = hn @ outw + outb : reduce po across the warp
    #pragma unroll
    for (int off = 16; off; off >>= 1)
        #pragma unroll
        for (int r = 0; r < 8; ++r)
            po[r] += __shfl_xor_sync(0xffffffffu, po[r], off);
    if (tx == 0) {
        float ob = outb[0];
        #pragma unroll
        for (int r = 0; r < 8; ++r)
            out[row0 + ty * 8 + r] = po[r] + ob;
    }
}

// ============================================================================
extern "C" void kernel_launch(void* const* d_in, const int* in_sizes, int n_in,
                              void* d_out, int out_size) {
    const float* data_nodes = (const float*)d_in[0];
    const float* data_te    = (const float*)d_in[1];
    const float* data_se    = (const float*)d_in[2];
    const float* h_n0 = (const float*)d_in[3];
    const float* c_n0 = (const float*)d_in[4];
    const float* h_t0 = (const float*)d_in[5];
    const float* c_t0 = (const float*)d_in[6];
    const float* h_s0 = (const float*)d_in[7];
    const float* c_s0 = (const float*)d_in[8];
    const int*   inc  = (const int*)d_in[9];
    const float* t_enc_w = (const float*)d_in[10];
    const float* t_enc_b = (const float*)d_in[11];
    const float* t_Wih   = (const float*)d_in[12];
    const float* t_Whh   = (const float*)d_in[13];
    const float* t_b     = (const float*)d_in[14];
    const float* s_enc_w = (const float*)d_in[15];
    const float* s_enc_b = (const float*)d_in[16];
    const float* s_Wih   = (const float*)d_in[17];
    const float* s_Whh   = (const float*)d_in[18];
    const float* s_b     = (const float*)d_in[19];
    const float* n_enc_w = (const float*)d_in[20];
    const float* n_enc_b = (const float*)d_in[21];
    const float* ee_w    = (const float*)d_in[22];
    const float* ee_b    = (const float*)d_in[23];
    const float* n_Wih   = (const float*)d_in[24];
    const float* n_Whh   = (const float*)d_in[25];
    const float* n_b     = (const float*)d_in[26];
    const float* out_w   = (const float*)d_in[27];
    const float* out_b   = (const float*)d_in[28];
    float* out = (float*)d_out;

    float *hs, *cs, *ht, *ct, *hn, *cn, *agg;
    cudaGetSymbolAddress((void**)&hs,  g_hs);
    cudaGetSymbolAddress((void**)&cs,  g_cs);
    cudaGetSymbolAddress((void**)&ht,  g_ht);
    cudaGetSymbolAddress((void**)&ct,  g_ct);
    cudaGetSymbolAddress((void**)&hn,  g_hn);
    cudaGetSymbolAddress((void**)&cn,  g_cn);
    cudaGetSymbolAddress((void**)&agg, g_agg);

    cudaMemcpyAsync(hs, h_s0, (size_t)EE * 64  * 4, cudaMemcpyDeviceToDevice);
    cudaMemcpyAsync(cs, c_s0, (size_t)EE * 64  * 4, cudaMemcpyDeviceToDevice);
    cudaMemcpyAsync(ht, h_t0, (size_t)NN * 64  * 4, cudaMemcpyDeviceToDevice);
    cudaMemcpyAsync(ct, c_t0, (size_t)NN * 64  * 4, cudaMemcpyDeviceToDevice);
    cudaMemcpyAsync(hn, h_n0, (size_t)NN * 128 * 4, cudaMemcpyDeviceToDevice);
    cudaMemcpyAsync(cn, c_n0, (size_t)NN * 128 * 4, cudaMemcpyDeviceToDevice);

    cudaFuncSetAttribute(node_kernel, cudaFuncAttributeMaxDynamicSharedMemorySize,
                         NODE_SMEM_BYTES);

    for (int t = 0; t < SSTEPS; ++t) {
        cudaMemsetAsync(agg, 0, (size_t)NN * 64 * 4);
        edge_lstm_kernel<<<EE / 64, 256>>>(data_se + (size_t)t * EE * 2,
                                           s_enc_w, s_enc_b, s_Wih, s_Whh, s_b,
                                           hs, cs, agg, inc);
        edge_lstm_kernel<<<NN / 64, 256>>>(data_te + (size_t)t * NN * 2,
                                           t_enc_w, t_enc_b, t_Wih, t_Whh, t_b,
                                           ht, ct, nullptr, nullptr);
        node_kernel<<<NN / 64, 256, NODE_SMEM_BYTES>>>(
            data_nodes + (size_t)t * NN,
            n_enc_w, n_enc_b, ee_w, ee_b, n_Wih, n_Whh, n_b, out_w, out_b,
            ht, agg, hn, cn, out + (size_t)t * NN);
    }
}